// round 8
// baseline (speedup 1.0000x reference)
#include <cuda_runtime.h>
#include <cuda_fp16.h>
#include <math.h>

// Problem constants: N=100000, D=128, E=1600000
#define NMAX 131072        // index fits 17 bits
#define DD   128
#define EMAX 1600000
#define NB   1184          // generic grids: 8 blocks/SM * 148
#define TPB  256
#define NTHREADS (NB * TPB)

#define NBE  296           // edge kernel: 2 blocks/SM (L1 residency for src slices)
#define TPBE 512

#define NBINS_MAX 1024     // bin = si >> 7  (128 rows = 32KB fp16 slice)

// Static device scratch (no allocations)
__device__ __half g_srch[100000 * DD];     // fp16 src table (row = 256B = 16 uint4)
__device__ __half g_dsth[100000 * DD];     // fp16 dst table
__device__ float  g_lik[EMAX];             // likelihood indexed by ORIGINAL edge id
__device__ unsigned long long g_pack[EMAX];// sorted (si | di<<17 | e<<34)
__device__ unsigned g_binTot[NBINS_MAX];   // histogram (zeroed by k_scan each call)
__device__ unsigned g_cursor[NBINS_MAX];   // scatter cursors
__device__ double g_p1[NB], g_p2[NB], g_p3[NB];
__device__ float  g_mu, g_inv, g_im;
__device__ unsigned g_c1, g_c2;            // monotonic arrival counters (replay-safe)

// ---------------------------------------------------------------------------
// K0: fp32->fp16 tables (.cg: keep L2-resident) + graph->float copy + src histogram
// ---------------------------------------------------------------------------
__global__ __launch_bounds__(TPB) void k_conv(
    const float* __restrict__ src, const float* __restrict__ dst,
    const int* __restrict__ gr, float* __restrict__ out,
    int total, int E, int Nn, int nbins)
{
    __shared__ unsigned sh_hist[NBINS_MAX];
    for (int i = threadIdx.x; i < nbins; i += TPB) sh_hist[i] = 0;
    __syncthreads();

    const int nt8 = total >> 3;
    const float4* __restrict__ s4 = (const float4*)src;
    const float4* __restrict__ d4 = (const float4*)dst;
    uint4* __restrict__ so = (uint4*)g_srch;
    uint4* __restrict__ dsto = (uint4*)g_dsth;

    const int tid = blockIdx.x * TPB + threadIdx.x;

    for (int i = tid; i < nt8; i += NTHREADS) {
        float4 a0 = __ldcs(s4 + 2 * i);
        float4 a1 = __ldcs(s4 + 2 * i + 1);
        union { __half2 h; unsigned u; } c;
        uint4 o;
        c.h = __floats2half2_rn(a0.x, a0.y); o.x = c.u;
        c.h = __floats2half2_rn(a0.z, a0.w); o.y = c.u;
        c.h = __floats2half2_rn(a1.x, a1.y); o.z = c.u;
        c.h = __floats2half2_rn(a1.z, a1.w); o.w = c.u;
        __stcg(so + i, o);

        float4 b0 = __ldcs(d4 + 2 * i);
        float4 b1 = __ldcs(d4 + 2 * i + 1);
        c.h = __floats2half2_rn(b0.x, b0.y); o.x = c.u;
        c.h = __floats2half2_rn(b0.z, b0.w); o.y = c.u;
        c.h = __floats2half2_rn(b1.x, b1.y); o.z = c.u;
        c.h = __floats2half2_rn(b1.z, b1.w); o.w = c.u;
        __stcg(dsto + i, o);
    }

    // graph row 0 copy + histogram of src bins
    for (int i = tid; i < E; i += NTHREADS) {
        int si = __ldcs(gr + i);
        __stcs(out + i, (float)si);
        int sc = min(max(si, 0), Nn - 1);
        atomicAdd(&sh_hist[sc >> 7], 1u);
    }
    // graph row 1 copy
    for (int i = tid; i < E; i += NTHREADS)
        __stcs(out + (size_t)E + i, (float)__ldcs(gr + (size_t)E + i));

    __syncthreads();
    for (int i = threadIdx.x; i < nbins; i += TPB)
        if (sh_hist[i]) atomicAdd(&g_binTot[i], sh_hist[i]);
}

// ---------------------------------------------------------------------------
// K1: exclusive scan of histogram -> cursors; zero histogram for next replay.
// ---------------------------------------------------------------------------
__global__ __launch_bounds__(NBINS_MAX) void k_scan(int nbins)
{
    __shared__ unsigned sh[NBINS_MAX];
    const int t = threadIdx.x;
    unsigned own = (t < nbins) ? g_binTot[t] : 0u;
    sh[t] = own;
    __syncthreads();
    for (int off = 1; off < NBINS_MAX; off <<= 1) {
        unsigned v = (t >= off) ? sh[t - off] : 0u;
        __syncthreads();
        sh[t] += v;
        __syncthreads();
    }
    if (t < nbins) {
        g_cursor[t] = sh[t] - own;   // exclusive prefix
        g_binTot[t] = 0u;            // reset for next call
    }
}

// ---------------------------------------------------------------------------
// K2: scatter edges into bin-sorted order as packed uint64.
// (intra-bin order nondeterministic; all consumers are e-indexed -> output deterministic)
// ---------------------------------------------------------------------------
__global__ __launch_bounds__(TPB) void k_scatter(
    const int* __restrict__ gr, int E, int Nn)
{
    const int tid = blockIdx.x * TPB + threadIdx.x;
    for (int e = tid; e < E; e += NTHREADS) {
        int si = min(max(__ldcs(gr + e), 0), Nn - 1);
        int di = min(max(__ldcs(gr + (size_t)E + e), 0), Nn - 1);
        unsigned pos = atomicAdd(&g_cursor[si >> 7], 1u);
        unsigned long long p = (unsigned long long)si
                             | ((unsigned long long)di << 17)
                             | ((unsigned long long)e  << 34);
        g_pack[pos] = p;
    }
}

// ---------------------------------------------------------------------------
// K3: bin-sorted gather + distance + likelihood (scatter-stored by orig id).
// 2 blocks/SM so src slices stay L1-resident; 16 lanes/edge, 2 edges/warp-step.
// ---------------------------------------------------------------------------
__global__ __launch_bounds__(TPBE) void k_edge(int E)
{
    const int lane  = threadIdx.x & 31;
    const int wid   = threadIdx.x >> 5;          // 0..15
    const int half_sel = lane & 16;
    const int lane15   = lane & 15;

    const int chunk = (E + NBE - 1) / NBE;
    const int bstart = blockIdx.x * chunk;
    const int bend   = min(E, bstart + chunk);

    const uint4* __restrict__ stab = (const uint4*)g_srch;
    const uint4* __restrict__ dtab = (const uint4*)g_dsth;

    for (int base = bstart + wid * 32; base < bend; base += (TPBE / 32) * 32) {
        const int m = min(32, bend - base);

        int si = 0, di = 0, eo = 0;
        if (lane < m) {
            unsigned long long p = __ldcs(g_pack + base + lane);
            si = (int)(p & 0x1FFFFu);
            di = (int)((p >> 17) & 0x1FFFFu);
            eo = (int)(p >> 34);
        }

        float acc = 0.0f;

        #pragma unroll 4
        for (int t = 0; t < 16; t++) {
            const int srcl = t | half_sel;
            const int s = __shfl_sync(0xffffffffu, si, srcl);
            const int d = __shfl_sync(0xffffffffu, di, srcl);

            uint4 av = __ldg(stab + (size_t)s * 16 + lane15);
            uint4 bv = __ldg(dtab + (size_t)d * 16 + lane15);
            const __half2* ah = (const __half2*)&av;
            const __half2* bh = (const __half2*)&bv;

            float p = 0.0f;
            #pragma unroll
            for (int i = 0; i < 4; i++) {
                float2 fa = __half22float2(ah[i]);
                float2 fb = __half22float2(bh[i]);
                float dx = fa.x - fb.x, dy = fa.y - fb.y;
                p = fmaf(dx, dx, fmaf(dy, dy, p));
            }
            #pragma unroll
            for (int o = 8; o; o >>= 1)
                p += __shfl_xor_sync(0xffffffffu, p, o);

            if (lane15 == t) acc = p;
        }

        if (lane < m) {
            float v = -__logf(fmaxf(acc, 1e-12f));
            __stcg(g_lik + eo, v);               // scattered 4B store
        }
    }
}

// ---------------------------------------------------------------------------
// K4: fixed-order stats over g_lik; last block publishes mu / inv_std.
// ---------------------------------------------------------------------------
__global__ __launch_bounds__(TPB) void k_stats(int E)
{
    const float4* __restrict__ lik4 = (const float4*)g_lik;
    const int E4  = E >> 2;
    const int tid = blockIdx.x * TPB + threadIdx.x;

    double a1 = 0.0, a2 = 0.0;
    for (int i = tid; i < E4; i += NTHREADS) {
        float4 l = lik4[i];
        a1 += (double)((l.x + l.y) + (l.z + l.w));
        a2 += (double)l.x * l.x + (double)l.y * l.y
            + (double)l.z * l.z + (double)l.w * l.w;
    }
    for (int e = E4 * 4 + tid; e < E; e += NTHREADS) {
        float v = g_lik[e];
        a1 += (double)v; a2 += (double)v * v;
    }

    __shared__ double sh1[TPB], shq[TPB];
    sh1[threadIdx.x] = a1; shq[threadIdx.x] = a2;
    __syncthreads();
    for (int st = TPB / 2; st; st >>= 1) {
        if (threadIdx.x < st) {
            sh1[threadIdx.x] += sh1[threadIdx.x + st];
            shq[threadIdx.x] += shq[threadIdx.x + st];
        }
        __syncthreads();
    }
    __shared__ int s_last;
    if (threadIdx.x == 0) {
        g_p1[blockIdx.x] = sh1[0];
        g_p2[blockIdx.x] = shq[0];
        __threadfence();
        unsigned old = atomicAdd(&g_c1, 1u);
        s_last = ((old % NB) == NB - 1);
    }
    __syncthreads();

    if (s_last) {
        double t1 = 0.0, t2 = 0.0;
        for (int i = threadIdx.x; i < NB; i += TPB) { t1 += g_p1[i]; t2 += g_p2[i]; }
        sh1[threadIdx.x] = t1; shq[threadIdx.x] = t2;
        __syncthreads();
        for (int st = TPB / 2; st; st >>= 1) {
            if (threadIdx.x < st) {
                sh1[threadIdx.x] += sh1[threadIdx.x + st];
                shq[threadIdx.x] += shq[threadIdx.x + st];
            }
            __syncthreads();
        }
        if (threadIdx.x == 0) {
            double mu  = sh1[0] / (double)E;
            double var = shq[0] / (double)E - mu * mu;
            g_mu  = (float)mu;
            g_inv = (float)rsqrt(var + 1e-5);
        }
    }
}

// ---------------------------------------------------------------------------
// K5: logits (stored) + sigmoid partial sums; last block publishes inv_mean.
// ---------------------------------------------------------------------------
__global__ __launch_bounds__(TPB) void k_logits(
    const float* __restrict__ bw, const float* __restrict__ bb,
    float* __restrict__ out, int E)
{
    const float mu = g_mu;
    const float wi = __ldg(bw) * g_inv;
    const float b  = __ldg(bb);

    const float4* __restrict__ lik4 = (const float4*)g_lik;
    float4* __restrict__ lg4 = (float4*)(out + 3LL * E);

    const int E4  = E >> 2;
    const int tid = blockIdx.x * TPB + threadIdx.x;
    double s = 0.0;

    for (int i = tid; i < E4; i += NTHREADS) {
        float4 l = lik4[i];
        float4 g;
        g.x = fmaf(wi, l.x - mu, b); g.y = fmaf(wi, l.y - mu, b);
        g.z = fmaf(wi, l.z - mu, b); g.w = fmaf(wi, l.w - mu, b);
        __stcs(lg4 + i, g);
        s += (double)((1.0f / (1.0f + __expf(-g.x)) + 1.0f / (1.0f + __expf(-g.y))) +
                      (1.0f / (1.0f + __expf(-g.z)) + 1.0f / (1.0f + __expf(-g.w))));
    }
    for (int e = E4 * 4 + tid; e < E; e += NTHREADS) {
        float lg = fmaf(wi, g_lik[e] - mu, b);
        out[3LL * E + e] = lg;
        s += (double)(1.0f / (1.0f + __expf(-lg)));
    }

    __shared__ double sh[TPB];
    sh[threadIdx.x] = s;
    __syncthreads();
    for (int st = TPB / 2; st; st >>= 1) {
        if (threadIdx.x < st) sh[threadIdx.x] += sh[threadIdx.x + st];
        __syncthreads();
    }
    __shared__ int s_last;
    if (threadIdx.x == 0) {
        g_p3[blockIdx.x] = sh[0];
        __threadfence();
        unsigned old = atomicAdd(&g_c2, 1u);
        s_last = ((old % NB) == NB - 1);
    }
    __syncthreads();

    if (s_last) {
        double t = 0.0;
        for (int i = threadIdx.x; i < NB; i += TPB) t += g_p3[i];
        sh[threadIdx.x] = t;
        __syncthreads();
        for (int st = TPB / 2; st; st >>= 1) {
            if (threadIdx.x < st) sh[threadIdx.x] += sh[threadIdx.x + st];
            __syncthreads();
        }
        if (threadIdx.x == 0) g_im = (float)((double)E / sh[0]);
    }
}

// ---------------------------------------------------------------------------
// K6: edge weights (sigmoid recomputed from L2-hot logits * inv_mean)
// ---------------------------------------------------------------------------
__global__ __launch_bounds__(TPB) void k_ew(float* __restrict__ out, int E)
{
    const float im = g_im;

    const float4* __restrict__ lg4 = (const float4*)(out + 3LL * E);
    float4* __restrict__ ew4 = (float4*)(out + 2LL * E);

    const int E4  = E >> 2;
    const int tid = blockIdx.x * TPB + threadIdx.x;

    for (int i = tid; i < E4; i += NTHREADS) {
        float4 g = __ldcs(lg4 + i);
        float4 v;
        v.x = im / (1.0f + __expf(-g.x)); v.y = im / (1.0f + __expf(-g.y));
        v.z = im / (1.0f + __expf(-g.z)); v.w = im / (1.0f + __expf(-g.w));
        __stcs(ew4 + i, v);
    }
    for (int e = E4 * 4 + tid; e < E; e += NTHREADS)
        out[2LL * E + e] = im / (1.0f + __expf(-out[3LL * E + e]));
}

// ---------------------------------------------------------------------------
extern "C" void kernel_launch(void* const* d_in, const int* in_sizes, int n_in,
                              void* d_out, int out_size)
{
    const float* src = (const float*)d_in[0];
    const float* dst = (const float*)d_in[1];
    const int*   gr  = (const int*)d_in[2];
    const float* bw  = (const float*)d_in[3];
    const float* bb  = (const float*)d_in[4];
    float* out = (float*)d_out;

    const int E  = in_sizes[2] / 2;
    const int Nn = in_sizes[0] / DD;
    const int total = min(in_sizes[0], 100000 * DD);
    const int nbins = min((Nn + 127) >> 7, NBINS_MAX);

    k_conv   <<<NB,  TPB >>>(src, dst, gr, out, total, E, Nn, nbins);
    k_scan   <<<1,   NBINS_MAX>>>(nbins);
    k_scatter<<<NB,  TPB >>>(gr, E, Nn);
    k_edge   <<<NBE, TPBE>>>(E);
    k_stats  <<<NB,  TPB >>>(E);
    k_logits <<<NB,  TPB >>>(bw, bb, out, E);
    k_ew     <<<NB,  TPB >>>(out, E);
}

// round 9
// speedup vs baseline: 1.7710x; 1.7710x over previous
#include <cuda_runtime.h>
#include <cuda_fp16.h>
#include <math.h>

// Problem constants: N=100000, D=128, E=1600000
#define DD   128
#define EMAX 1600000
#define NB   1184          // generic grids: 8 blocks/SM * 148
#define TPB  256
#define NTHREADS (NB * TPB)

#define NBE  444           // edge kernel: 3 blocks/SM
#define TPBE 512

#define NBINS_MAX 1024     // bin = si >> 7 (128 rows = 32KB fp16 slice)
#define CPAD 32            // counter padding: 32 uints = 128B -> full LTS slice spread

// Static device scratch (no allocations)
__device__ __half g_srch[100000 * DD];
__device__ __half g_dsth[100000 * DD];
__device__ float  g_lik[EMAX];                    // likelihood by ORIGINAL edge id
__device__ unsigned long long g_pack[EMAX];       // bin-sorted (si | di<<17 | e<<34)
__device__ unsigned g_binTot[NBINS_MAX * CPAD];   // padded histogram
__device__ unsigned g_cursor[NBINS_MAX * CPAD];   // padded scatter cursors
__device__ double g_p1[NB], g_p2[NB], g_p3[NB];
__device__ float  g_mu, g_inv, g_im;
__device__ unsigned g_c1, g_c2;                   // monotonic counters (replay-safe)

// ---------------------------------------------------------------------------
// K0: fp32->fp16 tables (.cg) + gr row0 copy + src histogram (padded global)
// ---------------------------------------------------------------------------
__global__ __launch_bounds__(TPB) void k_conv(
    const float* __restrict__ src, const float* __restrict__ dst,
    const int* __restrict__ gr, float* __restrict__ out,
    int total, int E, int Nn, int nbins)
{
    __shared__ unsigned sh_hist[NBINS_MAX];
    for (int i = threadIdx.x; i < nbins; i += TPB) sh_hist[i] = 0;
    __syncthreads();

    const int nt8 = total >> 3;
    const float4* __restrict__ s4 = (const float4*)src;
    const float4* __restrict__ d4 = (const float4*)dst;
    uint4* __restrict__ so = (uint4*)g_srch;
    uint4* __restrict__ dsto = (uint4*)g_dsth;

    const int tid = blockIdx.x * TPB + threadIdx.x;

    for (int i = tid; i < nt8; i += NTHREADS) {
        float4 a0 = __ldcs(s4 + 2 * i);
        float4 a1 = __ldcs(s4 + 2 * i + 1);
        union { __half2 h; unsigned u; } c;
        uint4 o;
        c.h = __floats2half2_rn(a0.x, a0.y); o.x = c.u;
        c.h = __floats2half2_rn(a0.z, a0.w); o.y = c.u;
        c.h = __floats2half2_rn(a1.x, a1.y); o.z = c.u;
        c.h = __floats2half2_rn(a1.z, a1.w); o.w = c.u;
        __stcg(so + i, o);

        float4 b0 = __ldcs(d4 + 2 * i);
        float4 b1 = __ldcs(d4 + 2 * i + 1);
        c.h = __floats2half2_rn(b0.x, b0.y); o.x = c.u;
        c.h = __floats2half2_rn(b0.z, b0.w); o.y = c.u;
        c.h = __floats2half2_rn(b1.x, b1.y); o.z = c.u;
        c.h = __floats2half2_rn(b1.z, b1.w); o.w = c.u;
        __stcg(dsto + i, o);
    }

    // gr row 0: copy to out + histogram src bins
    for (int i = tid; i < E; i += NTHREADS) {
        int si = __ldcs(gr + i);
        __stcs(out + i, (float)si);
        int sc = min(max(si, 0), Nn - 1);
        atomicAdd(&sh_hist[sc >> 7], 1u);
    }

    __syncthreads();
    for (int i = threadIdx.x; i < nbins; i += TPB)
        if (sh_hist[i]) atomicAdd(&g_binTot[i * CPAD], sh_hist[i]);
}

// ---------------------------------------------------------------------------
// K1: exclusive scan -> padded cursors; reset histogram for next replay.
// ---------------------------------------------------------------------------
__global__ __launch_bounds__(NBINS_MAX) void k_scan(int nbins)
{
    __shared__ unsigned sh[NBINS_MAX];
    const int t = threadIdx.x;
    unsigned own = (t < nbins) ? g_binTot[t * CPAD] : 0u;
    sh[t] = own;
    __syncthreads();
    for (int off = 1; off < NBINS_MAX; off <<= 1) {
        unsigned v = (t >= off) ? sh[t - off] : 0u;
        __syncthreads();
        sh[t] += v;
        __syncthreads();
    }
    if (t < nbins) {
        g_cursor[t * CPAD] = sh[t] - own;   // exclusive prefix
        g_binTot[t * CPAD] = 0u;            // reset
    }
}

// ---------------------------------------------------------------------------
// K2: scatter edges into bin-sorted packed array + gr row1 copy.
// ---------------------------------------------------------------------------
__global__ __launch_bounds__(TPB) void k_scatter(
    const int* __restrict__ gr, float* __restrict__ out, int E, int Nn)
{
    const int tid = blockIdx.x * TPB + threadIdx.x;
    for (int e = tid; e < E; e += NTHREADS) {
        int s0 = __ldcs(gr + e);
        int d0 = __ldcs(gr + (size_t)E + e);
        __stcs(out + (size_t)E + e, (float)d0);      // gr row 1 copy
        int si = min(max(s0, 0), Nn - 1);
        int di = min(max(d0, 0), Nn - 1);
        unsigned pos = atomicAdd(&g_cursor[(si >> 7) * CPAD], 1u);
        g_pack[pos] = (unsigned long long)si
                    | ((unsigned long long)di << 17)
                    | ((unsigned long long)e  << 34);
    }
}

// ---------------------------------------------------------------------------
// K3: bin-sorted gather + distance + likelihood (stored by orig edge id).
// 3 blocks/SM x 512 threads; 16 lanes/edge, 2 edges/warp-step.
// ---------------------------------------------------------------------------
__global__ __launch_bounds__(TPBE, 3) void k_edge(int E)
{
    const int lane  = threadIdx.x & 31;
    const int wid   = threadIdx.x >> 5;          // 0..15
    const int half_sel = lane & 16;
    const int lane15   = lane & 15;

    const int chunk = (E + NBE - 1) / NBE;
    const int bstart = blockIdx.x * chunk;
    const int bend   = min(E, bstart + chunk);

    const uint4* __restrict__ stab = (const uint4*)g_srch;
    const uint4* __restrict__ dtab = (const uint4*)g_dsth;

    for (int base = bstart + wid * 32; base < bend; base += (TPBE / 32) * 32) {
        const int m = min(32, bend - base);

        int si = 0, di = 0, eo = 0;
        if (lane < m) {
            unsigned long long p = __ldcs(g_pack + base + lane);
            si = (int)(p & 0x1FFFFu);
            di = (int)((p >> 17) & 0x1FFFFu);
            eo = (int)(p >> 34);
        }

        float acc = 0.0f;

        #pragma unroll 4
        for (int t = 0; t < 16; t++) {
            const int srcl = t | half_sel;
            const int s = __shfl_sync(0xffffffffu, si, srcl);
            const int d = __shfl_sync(0xffffffffu, di, srcl);

            uint4 av = __ldg(stab + (size_t)s * 16 + lane15);
            uint4 bv = __ldg(dtab + (size_t)d * 16 + lane15);
            const __half2* ah = (const __half2*)&av;
            const __half2* bh = (const __half2*)&bv;

            float p = 0.0f;
            #pragma unroll
            for (int i = 0; i < 4; i++) {
                float2 fa = __half22float2(ah[i]);
                float2 fb = __half22float2(bh[i]);
                float dx = fa.x - fb.x, dy = fa.y - fb.y;
                p = fmaf(dx, dx, fmaf(dy, dy, p));
            }
            #pragma unroll
            for (int o = 8; o; o >>= 1)
                p += __shfl_xor_sync(0xffffffffu, p, o);

            if (lane15 == t) acc = p;
        }

        if (lane < m) {
            float v = -__logf(fmaxf(acc, 1e-12f));
            __stcg(g_lik + eo, v);
        }
    }
}

// ---------------------------------------------------------------------------
// K4: fixed-order stats over g_lik; last block publishes mu / inv_std.
// ---------------------------------------------------------------------------
__global__ __launch_bounds__(TPB) void k_stats(int E)
{
    const float4* __restrict__ lik4 = (const float4*)g_lik;
    const int E4  = E >> 2;
    const int tid = blockIdx.x * TPB + threadIdx.x;

    double a1 = 0.0, a2 = 0.0;
    for (int i = tid; i < E4; i += NTHREADS) {
        float4 l = lik4[i];
        a1 += (double)((l.x + l.y) + (l.z + l.w));
        a2 += (double)l.x * l.x + (double)l.y * l.y
            + (double)l.z * l.z + (double)l.w * l.w;
    }
    for (int e = E4 * 4 + tid; e < E; e += NTHREADS) {
        float v = g_lik[e];
        a1 += (double)v; a2 += (double)v * v;
    }

    __shared__ double sh1[TPB], shq[TPB];
    sh1[threadIdx.x] = a1; shq[threadIdx.x] = a2;
    __syncthreads();
    for (int st = TPB / 2; st; st >>= 1) {
        if (threadIdx.x < st) {
            sh1[threadIdx.x] += sh1[threadIdx.x + st];
            shq[threadIdx.x] += shq[threadIdx.x + st];
        }
        __syncthreads();
    }
    __shared__ int s_last;
    if (threadIdx.x == 0) {
        g_p1[blockIdx.x] = sh1[0];
        g_p2[blockIdx.x] = shq[0];
        __threadfence();
        unsigned old = atomicAdd(&g_c1, 1u);
        s_last = ((old % NB) == NB - 1);
    }
    __syncthreads();

    if (s_last) {
        double t1 = 0.0, t2 = 0.0;
        for (int i = threadIdx.x; i < NB; i += TPB) { t1 += g_p1[i]; t2 += g_p2[i]; }
        sh1[threadIdx.x] = t1; shq[threadIdx.x] = t2;
        __syncthreads();
        for (int st = TPB / 2; st; st >>= 1) {
            if (threadIdx.x < st) {
                sh1[threadIdx.x] += sh1[threadIdx.x + st];
                shq[threadIdx.x] += shq[threadIdx.x + st];
            }
            __syncthreads();
        }
        if (threadIdx.x == 0) {
            double mu  = sh1[0] / (double)E;
            double var = shq[0] / (double)E - mu * mu;
            g_mu  = (float)mu;
            g_inv = (float)rsqrt(var + 1e-5);
        }
    }
}

// ---------------------------------------------------------------------------
// K5: logits (stored) + sigmoid partial sums; last block publishes inv_mean.
// ---------------------------------------------------------------------------
__global__ __launch_bounds__(TPB) void k_logits(
    const float* __restrict__ bw, const float* __restrict__ bb,
    float* __restrict__ out, int E)
{
    const float mu = g_mu;
    const float wi = __ldg(bw) * g_inv;
    const float b  = __ldg(bb);

    const float4* __restrict__ lik4 = (const float4*)g_lik;
    float4* __restrict__ lg4 = (float4*)(out + 3LL * E);

    const int E4  = E >> 2;
    const int tid = blockIdx.x * TPB + threadIdx.x;
    double s = 0.0;

    for (int i = tid; i < E4; i += NTHREADS) {
        float4 l = lik4[i];
        float4 g;
        g.x = fmaf(wi, l.x - mu, b); g.y = fmaf(wi, l.y - mu, b);
        g.z = fmaf(wi, l.z - mu, b); g.w = fmaf(wi, l.w - mu, b);
        __stcs(lg4 + i, g);
        s += (double)((1.0f / (1.0f + __expf(-g.x)) + 1.0f / (1.0f + __expf(-g.y))) +
                      (1.0f / (1.0f + __expf(-g.z)) + 1.0f / (1.0f + __expf(-g.w))));
    }
    for (int e = E4 * 4 + tid; e < E; e += NTHREADS) {
        float lg = fmaf(wi, g_lik[e] - mu, b);
        out[3LL * E + e] = lg;
        s += (double)(1.0f / (1.0f + __expf(-lg)));
    }

    __shared__ double sh[TPB];
    sh[threadIdx.x] = s;
    __syncthreads();
    for (int st = TPB / 2; st; st >>= 1) {
        if (threadIdx.x < st) sh[threadIdx.x] += sh[threadIdx.x + st];
        __syncthreads();
    }
    __shared__ int s_last;
    if (threadIdx.x == 0) {
        g_p3[blockIdx.x] = sh[0];
        __threadfence();
        unsigned old = atomicAdd(&g_c2, 1u);
        s_last = ((old % NB) == NB - 1);
    }
    __syncthreads();

    if (s_last) {
        double t = 0.0;
        for (int i = threadIdx.x; i < NB; i += TPB) t += g_p3[i];
        sh[threadIdx.x] = t;
        __syncthreads();
        for (int st = TPB / 2; st; st >>= 1) {
            if (threadIdx.x < st) sh[threadIdx.x] += sh[threadIdx.x + st];
            __syncthreads();
        }
        if (threadIdx.x == 0) g_im = (float)((double)E / sh[0]);
    }
}

// ---------------------------------------------------------------------------
// K6: edge weights (sigmoid recomputed from L2-hot logits * inv_mean)
// ---------------------------------------------------------------------------
__global__ __launch_bounds__(TPB) void k_ew(float* __restrict__ out, int E)
{
    const float im = g_im;

    const float4* __restrict__ lg4 = (const float4*)(out + 3LL * E);
    float4* __restrict__ ew4 = (float4*)(out + 2LL * E);

    const int E4  = E >> 2;
    const int tid = blockIdx.x * TPB + threadIdx.x;

    for (int i = tid; i < E4; i += NTHREADS) {
        float4 g = __ldcs(lg4 + i);
        float4 v;
        v.x = im / (1.0f + __expf(-g.x)); v.y = im / (1.0f + __expf(-g.y));
        v.z = im / (1.0f + __expf(-g.z)); v.w = im / (1.0f + __expf(-g.w));
        __stcs(ew4 + i, v);
    }
    for (int e = E4 * 4 + tid; e < E; e += NTHREADS)
        out[2LL * E + e] = im / (1.0f + __expf(-out[3LL * E + e]));
}

// ---------------------------------------------------------------------------
extern "C" void kernel_launch(void* const* d_in, const int* in_sizes, int n_in,
                              void* d_out, int out_size)
{
    const float* src = (const float*)d_in[0];
    const float* dst = (const float*)d_in[1];
    const int*   gr  = (const int*)d_in[2];
    const float* bw  = (const float*)d_in[3];
    const float* bb  = (const float*)d_in[4];
    float* out = (float*)d_out;

    const int E  = in_sizes[2] / 2;
    const int Nn = in_sizes[0] / DD;
    const int total = min(in_sizes[0], 100000 * DD);
    const int nbins = min((Nn + 127) >> 7, NBINS_MAX);

    k_conv   <<<NB,  TPB >>>(src, dst, gr, out, total, E, Nn, nbins);
    k_scan   <<<1,   NBINS_MAX>>>(nbins);
    k_scatter<<<NB,  TPB >>>(gr, out, E, Nn);
    k_edge   <<<NBE, TPBE>>>(E);
    k_stats  <<<NB,  TPB >>>(E);
    k_logits <<<NB,  TPB >>>(bw, bb, out, E);
    k_ew     <<<NB,  TPB >>>(out, E);
}

// round 10
// speedup vs baseline: 1.9599x; 1.1067x over previous
#include <cuda_runtime.h>
#include <cuda_fp16.h>
#include <math.h>

// Problem constants: N=100000, D=128, E=1600000
#define DD   128
#define EMAX 1600000
#define NB   1184
#define TPB  256
#define NTHREADS (NB * TPB)

#define NBE  444           // edge kernel: 3 blocks/SM x 512
#define TPBE 512

#define NBH  148           // histogram blocks
#define TPBH 1024
#define NBS  296           // scatter blocks (2/SM)
#define TPBS 1024

#define NBINS_MAX 1024     // bin = si >> 7 (128 rows = 32KB fp16 slice)
#define CPAD 32            // pad counters to 128B for LTS slice spread

// Static device scratch (no allocations)
__device__ __half g_srch[100000 * DD];
__device__ __half g_dsth[100000 * DD];
__device__ float  g_lik[EMAX];                    // likelihood by ORIGINAL edge id
__device__ unsigned long long g_pack[EMAX];       // bin-sorted (si | di<<17 | e<<34)
__device__ unsigned g_binTot[NBINS_MAX * CPAD];   // padded histogram totals
__device__ unsigned g_cursor[NBINS_MAX * CPAD];   // padded reservation cursors
__device__ double g_p1[NB], g_p2[NB], g_p3[NB];
__device__ float  g_mu, g_inv, g_im;
__device__ unsigned g_c1, g_c2;                   // monotonic counters (replay-safe)

// ---------------------------------------------------------------------------
// K0: fp32 -> fp16 tables only (pure streaming conversion)
// ---------------------------------------------------------------------------
__global__ __launch_bounds__(TPB) void k_conv(
    const float* __restrict__ src, const float* __restrict__ dst, int total)
{
    const int nt8 = total >> 3;
    const float4* __restrict__ s4 = (const float4*)src;
    const float4* __restrict__ d4 = (const float4*)dst;
    uint4* __restrict__ so = (uint4*)g_srch;
    uint4* __restrict__ dsto = (uint4*)g_dsth;

    const int tid = blockIdx.x * TPB + threadIdx.x;

    for (int i = tid; i < nt8; i += NTHREADS) {
        float4 a0 = __ldcs(s4 + 2 * i);
        float4 a1 = __ldcs(s4 + 2 * i + 1);
        union { __half2 h; unsigned u; } c;
        uint4 o;
        c.h = __floats2half2_rn(a0.x, a0.y); o.x = c.u;
        c.h = __floats2half2_rn(a0.z, a0.w); o.y = c.u;
        c.h = __floats2half2_rn(a1.x, a1.y); o.z = c.u;
        c.h = __floats2half2_rn(a1.z, a1.w); o.w = c.u;
        __stcg(so + i, o);

        float4 b0 = __ldcs(d4 + 2 * i);
        float4 b1 = __ldcs(d4 + 2 * i + 1);
        c.h = __floats2half2_rn(b0.x, b0.y); o.x = c.u;
        c.h = __floats2half2_rn(b0.z, b0.w); o.y = c.u;
        c.h = __floats2half2_rn(b1.x, b1.y); o.z = c.u;
        c.h = __floats2half2_rn(b1.z, b1.w); o.w = c.u;
        __stcg(dsto + i, o);
    }
}

// ---------------------------------------------------------------------------
// K1: global bin histogram — 148 fat blocks, shared agg, 148 global adds/bin
// ---------------------------------------------------------------------------
__global__ __launch_bounds__(TPBH) void k_hist(
    const int* __restrict__ gr, int E, int Nn)
{
    __shared__ unsigned h[NBINS_MAX];
    for (int i = threadIdx.x; i < NBINS_MAX; i += TPBH) h[i] = 0;
    __syncthreads();

    const int chunk = (E + NBH - 1) / NBH;
    const int s = blockIdx.x * chunk;
    const int e = min(E, s + chunk);
    for (int i = s + threadIdx.x; i < e; i += TPBH) {
        int si = min(max(__ldcs(gr + i), 0), Nn - 1);
        atomicAdd(&h[si >> 7], 1u);
    }
    __syncthreads();
    for (int i = threadIdx.x; i < NBINS_MAX; i += TPBH)
        if (h[i]) atomicAdd(&g_binTot[i * CPAD], h[i]);
}

// ---------------------------------------------------------------------------
// K2: exclusive scan -> reservation cursors; reset totals for next replay.
// ---------------------------------------------------------------------------
__global__ __launch_bounds__(NBINS_MAX) void k_scan()
{
    __shared__ unsigned sh[NBINS_MAX];
    const int t = threadIdx.x;
    unsigned own = g_binTot[t * CPAD];
    sh[t] = own;
    __syncthreads();
    for (int off = 1; off < NBINS_MAX; off <<= 1) {
        unsigned v = (t >= off) ? sh[t - off] : 0u;
        __syncthreads();
        sh[t] += v;
        __syncthreads();
    }
    g_cursor[t * CPAD] = sh[t] - own;   // exclusive prefix = bin base
    g_binTot[t * CPAD] = 0u;            // reset
}

// ---------------------------------------------------------------------------
// K3: block-aggregated scatter + graph->float copies.
// One global atomic per (block,bin); placement via shared cursors.
// ---------------------------------------------------------------------------
__global__ __launch_bounds__(TPBS) void k_scatter(
    const int* __restrict__ gr, float* __restrict__ out, int E, int Nn)
{
    __shared__ unsigned hist[NBINS_MAX];   // phase1 counts -> phase3 local cursor
    __shared__ unsigned base[NBINS_MAX];

    for (int i = threadIdx.x; i < NBINS_MAX; i += TPBS) hist[i] = 0;
    __syncthreads();

    const int chunk = (E + NBS - 1) / NBS;
    const int s = blockIdx.x * chunk;
    const int eend = min(E, s + chunk);

    // phase 1: local counts
    for (int i = s + threadIdx.x; i < eend; i += TPBS) {
        int si = min(max(__ldcs(gr + i), 0), Nn - 1);
        atomicAdd(&hist[si >> 7], 1u);
    }
    __syncthreads();

    // phase 2: reserve contiguous global ranges (1 atomic per present bin)
    for (int i = threadIdx.x; i < NBINS_MAX; i += TPBS) {
        unsigned c = hist[i];
        if (c) base[i] = atomicAdd(&g_cursor[i * CPAD], c);
        hist[i] = 0;                        // reuse as local cursor
    }
    __syncthreads();

    // phase 3: place edges + graph copies
    for (int i = s + threadIdx.x; i < eend; i += TPBS) {
        int s0 = __ldcs(gr + i);
        int d0 = __ldcs(gr + (size_t)E + i);
        __stcs(out + i, (float)s0);
        __stcs(out + (size_t)E + i, (float)d0);
        int si = min(max(s0, 0), Nn - 1);
        int di = min(max(d0, 0), Nn - 1);
        int bin = si >> 7;
        unsigned pos = base[bin] + atomicAdd(&hist[bin], 1u);
        g_pack[pos] = (unsigned long long)si
                    | ((unsigned long long)di << 17)
                    | ((unsigned long long)i  << 34);
    }
}

// ---------------------------------------------------------------------------
// K4: bin-sorted gather + distance + likelihood (stored by orig edge id).
// hsub2 diff (1 instr / 2 elems) to cut issue pressure.
// ---------------------------------------------------------------------------
__global__ __launch_bounds__(TPBE, 3) void k_edge(int E)
{
    const int lane  = threadIdx.x & 31;
    const int wid   = threadIdx.x >> 5;
    const int half_sel = lane & 16;
    const int lane15   = lane & 15;

    const int chunk = (E + NBE - 1) / NBE;
    const int bstart = blockIdx.x * chunk;
    const int bend   = min(E, bstart + chunk);

    const uint4* __restrict__ stab = (const uint4*)g_srch;
    const uint4* __restrict__ dtab = (const uint4*)g_dsth;

    for (int base = bstart + wid * 32; base < bend; base += (TPBE / 32) * 32) {
        const int m = min(32, bend - base);

        int si = 0, di = 0, eo = 0;
        if (lane < m) {
            unsigned long long p = __ldcs(g_pack + base + lane);
            si = (int)(p & 0x1FFFFu);
            di = (int)((p >> 17) & 0x1FFFFu);
            eo = (int)(p >> 34);
        }

        float acc = 0.0f;

        #pragma unroll 4
        for (int t = 0; t < 16; t++) {
            const int srcl = t | half_sel;
            const int s = __shfl_sync(0xffffffffu, si, srcl);
            const int d = __shfl_sync(0xffffffffu, di, srcl);

            uint4 av = __ldg(stab + (size_t)s * 16 + lane15);
            uint4 bv = __ldg(dtab + (size_t)d * 16 + lane15);
            const __half2* ah = (const __half2*)&av;
            const __half2* bh = (const __half2*)&bv;

            float p = 0.0f;
            #pragma unroll
            for (int i = 0; i < 4; i++) {
                __half2 df = __hsub2(ah[i], bh[i]);
                float2 fd = __half22float2(df);
                p = fmaf(fd.x, fd.x, fmaf(fd.y, fd.y, p));
            }
            #pragma unroll
            for (int o = 8; o; o >>= 1)
                p += __shfl_xor_sync(0xffffffffu, p, o);

            if (lane15 == t) acc = p;
        }

        if (lane < m) {
            float v = -__logf(fmaxf(acc, 1e-12f));
            __stcg(g_lik + eo, v);
        }
    }
}

// ---------------------------------------------------------------------------
// K5: fixed-order stats over g_lik; last block publishes mu / inv_std.
// ---------------------------------------------------------------------------
__global__ __launch_bounds__(TPB) void k_stats(int E)
{
    const float4* __restrict__ lik4 = (const float4*)g_lik;
    const int E4  = E >> 2;
    const int tid = blockIdx.x * TPB + threadIdx.x;

    double a1 = 0.0, a2 = 0.0;
    for (int i = tid; i < E4; i += NTHREADS) {
        float4 l = lik4[i];
        a1 += (double)((l.x + l.y) + (l.z + l.w));
        a2 += (double)l.x * l.x + (double)l.y * l.y
            + (double)l.z * l.z + (double)l.w * l.w;
    }
    for (int e = E4 * 4 + tid; e < E; e += NTHREADS) {
        float v = g_lik[e];
        a1 += (double)v; a2 += (double)v * v;
    }

    __shared__ double sh1[TPB], shq[TPB];
    sh1[threadIdx.x] = a1; shq[threadIdx.x] = a2;
    __syncthreads();
    for (int st = TPB / 2; st; st >>= 1) {
        if (threadIdx.x < st) {
            sh1[threadIdx.x] += sh1[threadIdx.x + st];
            shq[threadIdx.x] += shq[threadIdx.x + st];
        }
        __syncthreads();
    }
    __shared__ int s_last;
    if (threadIdx.x == 0) {
        g_p1[blockIdx.x] = sh1[0];
        g_p2[blockIdx.x] = shq[0];
        __threadfence();
        unsigned old = atomicAdd(&g_c1, 1u);
        s_last = ((old % NB) == NB - 1);
    }
    __syncthreads();

    if (s_last) {
        double t1 = 0.0, t2 = 0.0;
        for (int i = threadIdx.x; i < NB; i += TPB) { t1 += g_p1[i]; t2 += g_p2[i]; }
        sh1[threadIdx.x] = t1; shq[threadIdx.x] = t2;
        __syncthreads();
        for (int st = TPB / 2; st; st >>= 1) {
            if (threadIdx.x < st) {
                sh1[threadIdx.x] += sh1[threadIdx.x + st];
                shq[threadIdx.x] += shq[threadIdx.x + st];
            }
            __syncthreads();
        }
        if (threadIdx.x == 0) {
            double mu  = sh1[0] / (double)E;
            double var = shq[0] / (double)E - mu * mu;
            g_mu  = (float)mu;
            g_inv = (float)rsqrt(var + 1e-5);
        }
    }
}

// ---------------------------------------------------------------------------
// K6: logits (stored) + sigmoid partial sums; last block publishes inv_mean.
// ---------------------------------------------------------------------------
__global__ __launch_bounds__(TPB) void k_logits(
    const float* __restrict__ bw, const float* __restrict__ bb,
    float* __restrict__ out, int E)
{
    const float mu = g_mu;
    const float wi = __ldg(bw) * g_inv;
    const float b  = __ldg(bb);

    const float4* __restrict__ lik4 = (const float4*)g_lik;
    float4* __restrict__ lg4 = (float4*)(out + 3LL * E);

    const int E4  = E >> 2;
    const int tid = blockIdx.x * TPB + threadIdx.x;
    double s = 0.0;

    for (int i = tid; i < E4; i += NTHREADS) {
        float4 l = lik4[i];
        float4 g;
        g.x = fmaf(wi, l.x - mu, b); g.y = fmaf(wi, l.y - mu, b);
        g.z = fmaf(wi, l.z - mu, b); g.w = fmaf(wi, l.w - mu, b);
        __stcs(lg4 + i, g);
        s += (double)((1.0f / (1.0f + __expf(-g.x)) + 1.0f / (1.0f + __expf(-g.y))) +
                      (1.0f / (1.0f + __expf(-g.z)) + 1.0f / (1.0f + __expf(-g.w))));
    }
    for (int e = E4 * 4 + tid; e < E; e += NTHREADS) {
        float lg = fmaf(wi, g_lik[e] - mu, b);
        out[3LL * E + e] = lg;
        s += (double)(1.0f / (1.0f + __expf(-lg)));
    }

    __shared__ double sh[TPB];
    sh[threadIdx.x] = s;
    __syncthreads();
    for (int st = TPB / 2; st; st >>= 1) {
        if (threadIdx.x < st) sh[threadIdx.x] += sh[threadIdx.x + st];
        __syncthreads();
    }
    __shared__ int s_last;
    if (threadIdx.x == 0) {
        g_p3[blockIdx.x] = sh[0];
        __threadfence();
        unsigned old = atomicAdd(&g_c2, 1u);
        s_last = ((old % NB) == NB - 1);
    }
    __syncthreads();

    if (s_last) {
        double t = 0.0;
        for (int i = threadIdx.x; i < NB; i += TPB) t += g_p3[i];
        sh[threadIdx.x] = t;
        __syncthreads();
        for (int st = TPB / 2; st; st >>= 1) {
            if (threadIdx.x < st) sh[threadIdx.x] += sh[threadIdx.x + st];
            __syncthreads();
        }
        if (threadIdx.x == 0) g_im = (float)((double)E / sh[0]);
    }
}

// ---------------------------------------------------------------------------
// K7: edge weights (sigmoid recomputed from L2-hot logits * inv_mean)
// ---------------------------------------------------------------------------
__global__ __launch_bounds__(TPB) void k_ew(float* __restrict__ out, int E)
{
    const float im = g_im;

    const float4* __restrict__ lg4 = (const float4*)(out + 3LL * E);
    float4* __restrict__ ew4 = (float4*)(out + 2LL * E);

    const int E4  = E >> 2;
    const int tid = blockIdx.x * TPB + threadIdx.x;

    for (int i = tid; i < E4; i += NTHREADS) {
        float4 g = __ldcs(lg4 + i);
        float4 v;
        v.x = im / (1.0f + __expf(-g.x)); v.y = im / (1.0f + __expf(-g.y));
        v.z = im / (1.0f + __expf(-g.z)); v.w = im / (1.0f + __expf(-g.w));
        __stcs(ew4 + i, v);
    }
    for (int e = E4 * 4 + tid; e < E; e += NTHREADS)
        out[2LL * E + e] = im / (1.0f + __expf(-out[3LL * E + e]));
}

// ---------------------------------------------------------------------------
extern "C" void kernel_launch(void* const* d_in, const int* in_sizes, int n_in,
                              void* d_out, int out_size)
{
    const float* src = (const float*)d_in[0];
    const float* dst = (const float*)d_in[1];
    const int*   gr  = (const int*)d_in[2];
    const float* bw  = (const float*)d_in[3];
    const float* bb  = (const float*)d_in[4];
    float* out = (float*)d_out;

    const int E  = in_sizes[2] / 2;
    const int Nn = in_sizes[0] / DD;
    const int total = min(in_sizes[0], 100000 * DD);

    k_conv   <<<NB,  TPB >>>(src, dst, total);
    k_hist   <<<NBH, TPBH>>>(gr, E, Nn);
    k_scan   <<<1,   NBINS_MAX>>>();
    k_scatter<<<NBS, TPBS>>>(gr, out, E, Nn);
    k_edge   <<<NBE, TPBE>>>(E);
    k_stats  <<<NB,  TPB >>>(E);
    k_logits <<<NB,  TPB >>>(bw, bb, out, E);
    k_ew     <<<NB,  TPB >>>(out, E);
}

// round 11
// speedup vs baseline: 2.5631x; 1.3078x over previous
#include <cuda_runtime.h>
#include <cuda_fp16.h>
#include <math.h>

// Problem constants: N=100000, D=128, E=1600000
#define DD   128
#define EMAX 1600000
#define NB   1184          // 8 blocks/SM * 148
#define TPB  256
#define NTHREADS (NB * TPB)

// Static device scratch (no allocations)
__device__ __half g_srch[100000 * DD];  // fp16 src table (row = 256B = 16 uint4)
__device__ __half g_dsth[100000 * DD];  // fp16 dst table
__device__ float  g_lik[EMAX];          // likelihood (k_edge -> k_logits)
__device__ double g_p1[NB], g_p2[NB], g_p3[NB];
__device__ float  g_mu, g_inv, g_im;
__device__ unsigned g_c1, g_c2;         // monotonic arrival counters (replay-safe)

// ---------------------------------------------------------------------------
// K0: fp32 -> fp16 tables only (pure streaming conversion; .cg keeps tables
// L2-resident for the gather kernel)
// ---------------------------------------------------------------------------
__global__ __launch_bounds__(TPB) void k_conv(
    const float* __restrict__ src, const float* __restrict__ dst, int total)
{
    const int nt8 = total >> 3;
    const float4* __restrict__ s4 = (const float4*)src;
    const float4* __restrict__ d4 = (const float4*)dst;
    uint4* __restrict__ so = (uint4*)g_srch;
    uint4* __restrict__ dsto = (uint4*)g_dsth;

    const int tid = blockIdx.x * TPB + threadIdx.x;

    for (int i = tid; i < nt8; i += NTHREADS) {
        float4 a0 = __ldcs(s4 + 2 * i);
        float4 a1 = __ldcs(s4 + 2 * i + 1);
        union { __half2 h; unsigned u; } c;
        uint4 o;
        c.h = __floats2half2_rn(a0.x, a0.y); o.x = c.u;
        c.h = __floats2half2_rn(a0.z, a0.w); o.y = c.u;
        c.h = __floats2half2_rn(a1.x, a1.y); o.z = c.u;
        c.h = __floats2half2_rn(a1.z, a1.w); o.w = c.u;
        __stcg(so + i, o);

        float4 b0 = __ldcs(d4 + 2 * i);
        float4 b1 = __ldcs(d4 + 2 * i + 1);
        c.h = __floats2half2_rn(b0.x, b0.y); o.x = c.u;
        c.h = __floats2half2_rn(b0.z, b0.w); o.y = c.u;
        c.h = __floats2half2_rn(b1.x, b1.y); o.z = c.u;
        c.h = __floats2half2_rn(b1.z, b1.w); o.w = c.u;
        __stcg(dsto + i, o);
    }
}

// ---------------------------------------------------------------------------
// K1: gather + squared distance + likelihood + fused stats; the last block
// to finish reduces all partials and publishes mu / inv_std.
// 16 lanes per edge (uint4 = 16B covers 256B fp16 row), 2 edges per warp-step.
// ---------------------------------------------------------------------------
__global__ __launch_bounds__(TPB) void k_edge(
    const int* __restrict__ gr, int E, int Nn)
{
    const int lane  = threadIdx.x & 31;
    const int gwarp = (blockIdx.x * TPB + threadIdx.x) >> 5;
    const int half_sel = lane & 16;
    const int lane15   = lane & 15;
    const int nwarps = NTHREADS / 32;

    const uint4* __restrict__ stab = (const uint4*)g_srch;
    const uint4* __restrict__ dtab = (const uint4*)g_dsth;

    double a1 = 0.0, a2 = 0.0;

    for (int base = gwarp * 32; base < E; base += nwarps * 32) {
        const int m = min(32, E - base);
        const int e = base + lane;

        int si = 0, di = 0;
        if (lane < m) {
            si = __ldcs(gr + e);
            di = __ldcs(gr + (size_t)E + e);
        }
        si = min(max(si, 0), Nn - 1);
        di = min(max(di, 0), Nn - 1);

        float acc = 0.0f;

        #pragma unroll 4
        for (int t = 0; t < 16; t++) {
            const int srcl = t | half_sel;
            const int s = __shfl_sync(0xffffffffu, si, srcl);
            const int d = __shfl_sync(0xffffffffu, di, srcl);

            uint4 av = __ldg(stab + (size_t)s * 16 + lane15);
            uint4 bv = __ldg(dtab + (size_t)d * 16 + lane15);
            const __half2* ah = (const __half2*)&av;
            const __half2* bh = (const __half2*)&bv;

            float p = 0.0f;
            #pragma unroll
            for (int i = 0; i < 4; i++) {
                float2 fa = __half22float2(ah[i]);
                float2 fb = __half22float2(bh[i]);
                float dx = fa.x - fb.x, dy = fa.y - fb.y;
                p = fmaf(dx, dx, fmaf(dy, dy, p));
            }
            #pragma unroll
            for (int o = 8; o; o >>= 1)
                p += __shfl_xor_sync(0xffffffffu, p, o);

            if (lane15 == t) acc = p;
        }

        if (lane < m) {
            float v = -__logf(fmaxf(acc, 1e-12f));
            __stcs(g_lik + e, v);
            a1 += (double)v;
            a2 += (double)v * (double)v;
        }
    }

    __shared__ double sh1[TPB], shq[TPB];
    sh1[threadIdx.x] = a1; shq[threadIdx.x] = a2;
    __syncthreads();
    for (int st = TPB / 2; st; st >>= 1) {
        if (threadIdx.x < st) {
            sh1[threadIdx.x] += sh1[threadIdx.x + st];
            shq[threadIdx.x] += shq[threadIdx.x + st];
        }
        __syncthreads();
    }
    __shared__ int s_last;
    if (threadIdx.x == 0) {
        g_p1[blockIdx.x] = sh1[0];
        g_p2[blockIdx.x] = shq[0];
        __threadfence();
        unsigned old = atomicAdd(&g_c1, 1u);
        s_last = ((old % NB) == NB - 1);       // replay-safe
    }
    __syncthreads();

    if (s_last) {                              // last block finalizes mu/inv_std
        double t1 = 0.0, t2 = 0.0;
        for (int i = threadIdx.x; i < NB; i += TPB) { t1 += g_p1[i]; t2 += g_p2[i]; }
        sh1[threadIdx.x] = t1; shq[threadIdx.x] = t2;
        __syncthreads();
        for (int st = TPB / 2; st; st >>= 1) {
            if (threadIdx.x < st) {
                sh1[threadIdx.x] += sh1[threadIdx.x + st];
                shq[threadIdx.x] += shq[threadIdx.x + st];
            }
            __syncthreads();
        }
        if (threadIdx.x == 0) {
            double mu  = sh1[0] / (double)E;
            double var = shq[0] / (double)E - mu * mu;
            g_mu  = (float)mu;
            g_inv = (float)rsqrt(var + 1e-5);
        }
    }
}

// ---------------------------------------------------------------------------
// K2: logits (stored) + sigmoid partial sums + graph row0 copy (absorbed in
// latency slack); last block publishes inv_mean.
// ---------------------------------------------------------------------------
__global__ __launch_bounds__(TPB) void k_logits(
    const int* __restrict__ gr,
    const float* __restrict__ bw, const float* __restrict__ bb,
    float* __restrict__ out, int E)
{
    const float mu = g_mu;
    const float wi = __ldg(bw) * g_inv;
    const float b  = __ldg(bb);

    const float4* __restrict__ lik4 = (const float4*)g_lik;
    float4* __restrict__ lg4 = (float4*)(out + 3LL * E);

    const int E4  = E >> 2;
    const int tid = blockIdx.x * TPB + threadIdx.x;
    double s = 0.0;

    for (int i = tid; i < E4; i += NTHREADS) {
        float4 l = lik4[i];
        float4 g;
        g.x = fmaf(wi, l.x - mu, b); g.y = fmaf(wi, l.y - mu, b);
        g.z = fmaf(wi, l.z - mu, b); g.w = fmaf(wi, l.w - mu, b);
        __stcs(lg4 + i, g);
        s += (double)((1.0f / (1.0f + __expf(-g.x)) + 1.0f / (1.0f + __expf(-g.y))) +
                      (1.0f / (1.0f + __expf(-g.z)) + 1.0f / (1.0f + __expf(-g.w))));
    }
    for (int e = E4 * 4 + tid; e < E; e += NTHREADS) {
        float lg = fmaf(wi, g_lik[e] - mu, b);
        out[3LL * E + e] = lg;
        s += (double)(1.0f / (1.0f + __expf(-lg)));
    }

    // graph row 0 -> float out (independent stream, fills latency slack)
    for (int i = tid; i < E; i += NTHREADS)
        __stcs(out + i, (float)__ldcs(gr + i));

    __shared__ double sh[TPB];
    sh[threadIdx.x] = s;
    __syncthreads();
    for (int st = TPB / 2; st; st >>= 1) {
        if (threadIdx.x < st) sh[threadIdx.x] += sh[threadIdx.x + st];
        __syncthreads();
    }
    __shared__ int s_last;
    if (threadIdx.x == 0) {
        g_p3[blockIdx.x] = sh[0];
        __threadfence();
        unsigned old = atomicAdd(&g_c2, 1u);
        s_last = ((old % NB) == NB - 1);
    }
    __syncthreads();

    if (s_last) {
        double t = 0.0;
        for (int i = threadIdx.x; i < NB; i += TPB) t += g_p3[i];
        sh[threadIdx.x] = t;
        __syncthreads();
        for (int st = TPB / 2; st; st >>= 1) {
            if (threadIdx.x < st) sh[threadIdx.x] += sh[threadIdx.x + st];
            __syncthreads();
        }
        if (threadIdx.x == 0) g_im = (float)((double)E / sh[0]);
    }
}

// ---------------------------------------------------------------------------
// K3: edge weights (sigmoid recomputed from L2-hot logits) + graph row1 copy.
// ---------------------------------------------------------------------------
__global__ __launch_bounds__(TPB) void k_ew(
    const int* __restrict__ gr, float* __restrict__ out, int E)
{
    const float im = g_im;

    const float4* __restrict__ lg4 = (const float4*)(out + 3LL * E);
    float4* __restrict__ ew4 = (float4*)(out + 2LL * E);

    const int E4  = E >> 2;
    const int tid = blockIdx.x * TPB + threadIdx.x;

    for (int i = tid; i < E4; i += NTHREADS) {
        float4 g = __ldcs(lg4 + i);
        float4 v;
        v.x = im / (1.0f + __expf(-g.x)); v.y = im / (1.0f + __expf(-g.y));
        v.z = im / (1.0f + __expf(-g.z)); v.w = im / (1.0f + __expf(-g.w));
        __stcs(ew4 + i, v);
    }
    for (int e = E4 * 4 + tid; e < E; e += NTHREADS)
        out[2LL * E + e] = im / (1.0f + __expf(-out[3LL * E + e]));

    // graph row 1 -> float out (independent stream, fills latency slack)
    for (int i = tid; i < E; i += NTHREADS)
        __stcs(out + (size_t)E + i, (float)__ldcs(gr + (size_t)E + i));
}

// ---------------------------------------------------------------------------
extern "C" void kernel_launch(void* const* d_in, const int* in_sizes, int n_in,
                              void* d_out, int out_size)
{
    const float* src = (const float*)d_in[0];
    const float* dst = (const float*)d_in[1];
    const int*   gr  = (const int*)d_in[2];
    const float* bw  = (const float*)d_in[3];
    const float* bb  = (const float*)d_in[4];
    float* out = (float*)d_out;

    const int E  = in_sizes[2] / 2;
    const int Nn = in_sizes[0] / DD;
    const int total = min(in_sizes[0], 100000 * DD);

    k_conv  <<<NB, TPB>>>(src, dst, total);
    k_edge  <<<NB, TPB>>>(gr, E, Nn);
    k_logits<<<NB, TPB>>>(gr, bw, bb, out, E);
    k_ew    <<<NB, TPB>>>(gr, out, E);
}

// round 12
// speedup vs baseline: 2.5986x; 1.0139x over previous
#include <cuda_runtime.h>
#include <cuda_fp16.h>
#include <math.h>

// Problem constants: N=100000, D=128, E=1600000
#define DD   128
#define EMAX 1600000
#define NB   1184          // 8 blocks/SM * 148
#define TPB  256
#define NTHREADS (NB * TPB)

#define PDL_WAIT()    asm volatile("griddepcontrol.wait;" ::: "memory")
#define PDL_TRIGGER() asm volatile("griddepcontrol.launch_dependents;" ::: "memory")

// Static device scratch (no allocations)
__device__ __half g_srch[100000 * DD];  // fp16 src table (row = 256B = 16 uint4)
__device__ __half g_dsth[100000 * DD];  // fp16 dst table
__device__ float  g_lik[EMAX];          // likelihood (k_edge -> k_logits)
__device__ double g_p1[NB], g_p2[NB], g_p3[NB];
__device__ float  g_mu, g_inv, g_im;
__device__ unsigned g_c1, g_c2;         // monotonic arrival counters (replay-safe)

// ---------------------------------------------------------------------------
// K0: fp32 -> fp16 tables (pure streaming; .cg keeps tables L2-resident)
// ---------------------------------------------------------------------------
__global__ __launch_bounds__(TPB) void k_conv(
    const float* __restrict__ src, const float* __restrict__ dst, int total)
{
    const int nt8 = total >> 3;
    const float4* __restrict__ s4 = (const float4*)src;
    const float4* __restrict__ d4 = (const float4*)dst;
    uint4* __restrict__ so = (uint4*)g_srch;
    uint4* __restrict__ dsto = (uint4*)g_dsth;

    const int tid = blockIdx.x * TPB + threadIdx.x;

    for (int i = tid; i < nt8; i += NTHREADS) {
        float4 a0 = __ldcs(s4 + 2 * i);
        float4 a1 = __ldcs(s4 + 2 * i + 1);
        union { __half2 h; unsigned u; } c;
        uint4 o;
        c.h = __floats2half2_rn(a0.x, a0.y); o.x = c.u;
        c.h = __floats2half2_rn(a0.z, a0.w); o.y = c.u;
        c.h = __floats2half2_rn(a1.x, a1.y); o.z = c.u;
        c.h = __floats2half2_rn(a1.z, a1.w); o.w = c.u;
        __stcg(so + i, o);

        float4 b0 = __ldcs(d4 + 2 * i);
        float4 b1 = __ldcs(d4 + 2 * i + 1);
        c.h = __floats2half2_rn(b0.x, b0.y); o.x = c.u;
        c.h = __floats2half2_rn(b0.z, b0.w); o.y = c.u;
        c.h = __floats2half2_rn(b1.x, b1.y); o.z = c.u;
        c.h = __floats2half2_rn(b1.z, b1.w); o.w = c.u;
        __stcg(dsto + i, o);
    }
    PDL_TRIGGER();
}

// ---------------------------------------------------------------------------
// K1: gather + distance + likelihood + fused stats; last block publishes
// mu / inv_std. Triggers dependents before the last-block reduce.
// ---------------------------------------------------------------------------
__global__ __launch_bounds__(TPB) void k_edge(
    const int* __restrict__ gr, int E, int Nn)
{
    const int lane  = threadIdx.x & 31;
    const int gwarp = (blockIdx.x * TPB + threadIdx.x) >> 5;
    const int half_sel = lane & 16;
    const int lane15   = lane & 15;
    const int nwarps = NTHREADS / 32;

    PDL_WAIT();    // tables must be converted

    const uint4* __restrict__ stab = (const uint4*)g_srch;
    const uint4* __restrict__ dtab = (const uint4*)g_dsth;

    double a1 = 0.0, a2 = 0.0;

    for (int base = gwarp * 32; base < E; base += nwarps * 32) {
        const int m = min(32, E - base);
        const int e = base + lane;

        int si = 0, di = 0;
        if (lane < m) {
            si = __ldcs(gr + e);
            di = __ldcs(gr + (size_t)E + e);
        }
        si = min(max(si, 0), Nn - 1);
        di = min(max(di, 0), Nn - 1);

        float acc = 0.0f;

        #pragma unroll 4
        for (int t = 0; t < 16; t++) {
            const int srcl = t | half_sel;
            const int s = __shfl_sync(0xffffffffu, si, srcl);
            const int d = __shfl_sync(0xffffffffu, di, srcl);

            uint4 av = __ldg(stab + (size_t)s * 16 + lane15);
            uint4 bv = __ldg(dtab + (size_t)d * 16 + lane15);
            const __half2* ah = (const __half2*)&av;
            const __half2* bh = (const __half2*)&bv;

            float p = 0.0f;
            #pragma unroll
            for (int i = 0; i < 4; i++) {
                float2 fa = __half22float2(ah[i]);
                float2 fb = __half22float2(bh[i]);
                float dx = fa.x - fb.x, dy = fa.y - fb.y;
                p = fmaf(dx, dx, fmaf(dy, dy, p));
            }
            #pragma unroll
            for (int o = 8; o; o >>= 1)
                p += __shfl_xor_sync(0xffffffffu, p, o);

            if (lane15 == t) acc = p;
        }

        if (lane < m) {
            float v = -__logf(fmaxf(acc, 1e-12f));
            __stcs(g_lik + e, v);
            a1 += (double)v;
            a2 += (double)v * (double)v;
        }
    }

    __shared__ double sh1[TPB], shq[TPB];
    sh1[threadIdx.x] = a1; shq[threadIdx.x] = a2;
    __syncthreads();
    for (int st = TPB / 2; st; st >>= 1) {
        if (threadIdx.x < st) {
            sh1[threadIdx.x] += sh1[threadIdx.x + st];
            shq[threadIdx.x] += shq[threadIdx.x + st];
        }
        __syncthreads();
    }
    __shared__ int s_last;
    if (threadIdx.x == 0) {
        g_p1[blockIdx.x] = sh1[0];
        g_p2[blockIdx.x] = shq[0];
        __threadfence();
        unsigned old = atomicAdd(&g_c1, 1u);
        s_last = ((old % NB) == NB - 1);       // replay-safe
    }
    __syncthreads();
    PDL_TRIGGER();   // k_logits can start its independent copy now

    if (s_last) {                              // last block finalizes mu/inv_std
        double t1 = 0.0, t2 = 0.0;
        for (int i = threadIdx.x; i < NB; i += TPB) { t1 += g_p1[i]; t2 += g_p2[i]; }
        sh1[threadIdx.x] = t1; shq[threadIdx.x] = t2;
        __syncthreads();
        for (int st = TPB / 2; st; st >>= 1) {
            if (threadIdx.x < st) {
                sh1[threadIdx.x] += sh1[threadIdx.x + st];
                shq[threadIdx.x] += shq[threadIdx.x + st];
            }
            __syncthreads();
        }
        if (threadIdx.x == 0) {
            double mu  = sh1[0] / (double)E;
            double var = shq[0] / (double)E - mu * mu;
            g_mu  = (float)mu;
            g_inv = (float)rsqrt(var + 1e-5);
        }
    }
}

// ---------------------------------------------------------------------------
// K2: graph row0 copy (pre-wait, overlaps k_edge tail) + logits + sigmoid
// partial sums; last block publishes inv_mean.
// ---------------------------------------------------------------------------
__global__ __launch_bounds__(TPB) void k_logits(
    const int* __restrict__ gr,
    const float* __restrict__ bw, const float* __restrict__ bb,
    float* __restrict__ out, int E)
{
    const int tid = blockIdx.x * TPB + threadIdx.x;

    // independent of k_edge: runs while k_edge finishes
    for (int i = tid; i < E; i += NTHREADS)
        __stcs(out + i, (float)__ldcs(gr + i));

    PDL_WAIT();    // g_mu / g_inv / g_lik now visible

    const float mu = g_mu;
    const float wi = __ldg(bw) * g_inv;
    const float b  = __ldg(bb);

    const float4* __restrict__ lik4 = (const float4*)g_lik;
    float4* __restrict__ lg4 = (float4*)(out + 3LL * E);

    const int E4 = E >> 2;
    double s = 0.0;

    for (int i = tid; i < E4; i += NTHREADS) {
        float4 l = lik4[i];
        float4 g;
        g.x = fmaf(wi, l.x - mu, b); g.y = fmaf(wi, l.y - mu, b);
        g.z = fmaf(wi, l.z - mu, b); g.w = fmaf(wi, l.w - mu, b);
        __stcs(lg4 + i, g);
        s += (double)((1.0f / (1.0f + __expf(-g.x)) + 1.0f / (1.0f + __expf(-g.y))) +
                      (1.0f / (1.0f + __expf(-g.z)) + 1.0f / (1.0f + __expf(-g.w))));
    }
    for (int e = E4 * 4 + tid; e < E; e += NTHREADS) {
        float lg = fmaf(wi, g_lik[e] - mu, b);
        out[3LL * E + e] = lg;
        s += (double)(1.0f / (1.0f + __expf(-lg)));
    }

    __shared__ double sh[TPB];
    sh[threadIdx.x] = s;
    __syncthreads();
    for (int st = TPB / 2; st; st >>= 1) {
        if (threadIdx.x < st) sh[threadIdx.x] += sh[threadIdx.x + st];
        __syncthreads();
    }
    __shared__ int s_last;
    if (threadIdx.x == 0) {
        g_p3[blockIdx.x] = sh[0];
        __threadfence();
        unsigned old = atomicAdd(&g_c2, 1u);
        s_last = ((old % NB) == NB - 1);
    }
    __syncthreads();
    PDL_TRIGGER();   // k_ew can start its independent copy now

    if (s_last) {
        double t = 0.0;
        for (int i = threadIdx.x; i < NB; i += TPB) t += g_p3[i];
        sh[threadIdx.x] = t;
        __syncthreads();
        for (int st = TPB / 2; st; st >>= 1) {
            if (threadIdx.x < st) sh[threadIdx.x] += sh[threadIdx.x + st];
            __syncthreads();
        }
        if (threadIdx.x == 0) g_im = (float)((double)E / sh[0]);
    }
}

// ---------------------------------------------------------------------------
// K3: graph row1 copy (pre-wait) + edge weights (sigmoid recomputed from
// L2-hot logits, scaled by inv_mean).
// ---------------------------------------------------------------------------
__global__ __launch_bounds__(TPB) void k_ew(
    const int* __restrict__ gr, float* __restrict__ out, int E)
{
    const int tid = blockIdx.x * TPB + threadIdx.x;

    // independent of k_logits' results
    for (int i = tid; i < E; i += NTHREADS)
        __stcs(out + (size_t)E + i, (float)__ldcs(gr + (size_t)E + i));

    PDL_WAIT();    // g_im and logits now visible

    const float im = g_im;
    const float4* __restrict__ lg4 = (const float4*)(out + 3LL * E);
    float4* __restrict__ ew4 = (float4*)(out + 2LL * E);

    const int E4 = E >> 2;
    for (int i = tid; i < E4; i += NTHREADS) {
        float4 g = __ldcs(lg4 + i);
        float4 v;
        v.x = im / (1.0f + __expf(-g.x)); v.y = im / (1.0f + __expf(-g.y));
        v.z = im / (1.0f + __expf(-g.z)); v.w = im / (1.0f + __expf(-g.w));
        __stcs(ew4 + i, v);
    }
    for (int e = E4 * 4 + tid; e < E; e += NTHREADS)
        out[2LL * E + e] = im / (1.0f + __expf(-out[3LL * E + e]));
}

// ---------------------------------------------------------------------------
template <typename... Args>
static inline void launch_pdl(void (*kern)(Args...), Args... args)
{
    cudaLaunchConfig_t cfg = {};
    cfg.gridDim  = dim3(NB, 1, 1);
    cfg.blockDim = dim3(TPB, 1, 1);
    cudaLaunchAttribute a[1];
    a[0].id = cudaLaunchAttributeProgrammaticStreamSerialization;
    a[0].val.programmaticStreamSerializationAllowed = 1;
    cfg.attrs = a;
    cfg.numAttrs = 1;
    cudaLaunchKernelEx(&cfg, kern, args...);
}

extern "C" void kernel_launch(void* const* d_in, const int* in_sizes, int n_in,
                              void* d_out, int out_size)
{
    const float* src = (const float*)d_in[0];
    const float* dst = (const float*)d_in[1];
    const int*   gr  = (const int*)d_in[2];
    const float* bw  = (const float*)d_in[3];
    const float* bb  = (const float*)d_in[4];
    float* out = (float*)d_out;

    const int E  = in_sizes[2] / 2;
    const int Nn = in_sizes[0] / DD;
    const int total = min(in_sizes[0], 100000 * DD);

    k_conv<<<NB, TPB>>>(src, dst, total);
    launch_pdl(k_edge, gr, E, Nn);
    launch_pdl(k_logits, gr, bw, bb, out, E);
    launch_pdl(k_ew, gr, out, E);
}

// round 13
// speedup vs baseline: 2.6572x; 1.0226x over previous
#include <cuda_runtime.h>
#include <cuda_fp16.h>
#include <math.h>

// Problem constants: N=100000, D=128, E=1600000
#define DD   128
#define EMAX 1600000
#define NB   1184          // 8 blocks/SM * 148
#define TPB  256
#define NTHREADS (NB * TPB)

#define PDL_WAIT()    asm volatile("griddepcontrol.wait;" ::: "memory")
#define PDL_TRIGGER() asm volatile("griddepcontrol.launch_dependents;" ::: "memory")

// Static device scratch (no allocations)
__device__ __half g_srch[100000 * DD];  // fp16 src table (row = 256B = 16 uint4)
__device__ __half g_dsth[100000 * DD];  // fp16 dst table
__device__ float  g_lik[EMAX];          // likelihood (k_edge -> k_logits)
__device__ double g_p1[NB], g_p2[NB], g_p3[NB];
__device__ float  g_mu, g_inv, g_im;
__device__ unsigned g_c1, g_c2;         // monotonic arrival counters (replay-safe)

// ---------------------------------------------------------------------------
// K0: fp32 -> fp16 tables (pure streaming; .cg keeps tables L2-resident).
// Unrolled x2 for load-level parallelism.
// ---------------------------------------------------------------------------
__global__ __launch_bounds__(TPB) void k_conv(
    const float* __restrict__ src, const float* __restrict__ dst, int total)
{
    const int nt8 = total >> 3;
    const float4* __restrict__ s4 = (const float4*)src;
    const float4* __restrict__ d4 = (const float4*)dst;
    uint4* __restrict__ so = (uint4*)g_srch;
    uint4* __restrict__ dsto = (uint4*)g_dsth;

    const int tid = blockIdx.x * TPB + threadIdx.x;

    for (int i0 = tid; i0 < nt8; i0 += 2 * NTHREADS) {
        const int i1 = i0 + NTHREADS;
        // batch all loads first (independent -> in flight together)
        float4 a0 = __ldcs(s4 + 2 * i0);
        float4 a1 = __ldcs(s4 + 2 * i0 + 1);
        float4 b0 = __ldcs(d4 + 2 * i0);
        float4 b1 = __ldcs(d4 + 2 * i0 + 1);
        float4 a2, a3, b2, b3;
        if (i1 < nt8) {
            a2 = __ldcs(s4 + 2 * i1);
            a3 = __ldcs(s4 + 2 * i1 + 1);
            b2 = __ldcs(d4 + 2 * i1);
            b3 = __ldcs(d4 + 2 * i1 + 1);
        }

        union { __half2 h; unsigned u; } c;
        uint4 o;
        c.h = __floats2half2_rn(a0.x, a0.y); o.x = c.u;
        c.h = __floats2half2_rn(a0.z, a0.w); o.y = c.u;
        c.h = __floats2half2_rn(a1.x, a1.y); o.z = c.u;
        c.h = __floats2half2_rn(a1.z, a1.w); o.w = c.u;
        __stcg(so + i0, o);
        c.h = __floats2half2_rn(b0.x, b0.y); o.x = c.u;
        c.h = __floats2half2_rn(b0.z, b0.w); o.y = c.u;
        c.h = __floats2half2_rn(b1.x, b1.y); o.z = c.u;
        c.h = __floats2half2_rn(b1.z, b1.w); o.w = c.u;
        __stcg(dsto + i0, o);

        if (i1 < nt8) {
            c.h = __floats2half2_rn(a2.x, a2.y); o.x = c.u;
            c.h = __floats2half2_rn(a2.z, a2.w); o.y = c.u;
            c.h = __floats2half2_rn(a3.x, a3.y); o.z = c.u;
            c.h = __floats2half2_rn(a3.z, a3.w); o.w = c.u;
            __stcg(so + i1, o);
            c.h = __floats2half2_rn(b2.x, b2.y); o.x = c.u;
            c.h = __floats2half2_rn(b2.z, b2.w); o.y = c.u;
            c.h = __floats2half2_rn(b3.x, b3.y); o.z = c.u;
            c.h = __floats2half2_rn(b3.z, b3.w); o.w = c.u;
            __stcg(dsto + i1, o);
        }
    }
    PDL_TRIGGER();
}

// ---------------------------------------------------------------------------
// K1: gather + distance + likelihood + fused stats; last block publishes
// mu / inv_std. Triggers dependents before the last-block reduce.
// ---------------------------------------------------------------------------
__global__ __launch_bounds__(TPB) void k_edge(
    const int* __restrict__ gr, int E, int Nn)
{
    const int lane  = threadIdx.x & 31;
    const int gwarp = (blockIdx.x * TPB + threadIdx.x) >> 5;
    const int half_sel = lane & 16;
    const int lane15   = lane & 15;
    const int nwarps = NTHREADS / 32;

    PDL_WAIT();    // tables must be converted

    const uint4* __restrict__ stab = (const uint4*)g_srch;
    const uint4* __restrict__ dtab = (const uint4*)g_dsth;

    double a1 = 0.0, a2 = 0.0;

    for (int base = gwarp * 32; base < E; base += nwarps * 32) {
        const int m = min(32, E - base);
        const int e = base + lane;

        int si = 0, di = 0;
        if (lane < m) {
            si = __ldcs(gr + e);
            di = __ldcs(gr + (size_t)E + e);
        }
        si = min(max(si, 0), Nn - 1);
        di = min(max(di, 0), Nn - 1);

        float acc = 0.0f;

        #pragma unroll 4
        for (int t = 0; t < 16; t++) {
            const int srcl = t | half_sel;
            const int s = __shfl_sync(0xffffffffu, si, srcl);
            const int d = __shfl_sync(0xffffffffu, di, srcl);

            uint4 av = __ldg(stab + (size_t)s * 16 + lane15);
            uint4 bv = __ldg(dtab + (size_t)d * 16 + lane15);
            const __half2* ah = (const __half2*)&av;
            const __half2* bh = (const __half2*)&bv;

            float p = 0.0f;
            #pragma unroll
            for (int i = 0; i < 4; i++) {
                float2 fa = __half22float2(ah[i]);
                float2 fb = __half22float2(bh[i]);
                float dx = fa.x - fb.x, dy = fa.y - fb.y;
                p = fmaf(dx, dx, fmaf(dy, dy, p));
            }
            #pragma unroll
            for (int o = 8; o; o >>= 1)
                p += __shfl_xor_sync(0xffffffffu, p, o);

            if (lane15 == t) acc = p;
        }

        if (lane < m) {
            float v = -__logf(fmaxf(acc, 1e-12f));
            __stcs(g_lik + e, v);
            a1 += (double)v;
            a2 += (double)v * (double)v;
        }
    }

    __shared__ double sh1[TPB], shq[TPB];
    sh1[threadIdx.x] = a1; shq[threadIdx.x] = a2;
    __syncthreads();
    for (int st = TPB / 2; st; st >>= 1) {
        if (threadIdx.x < st) {
            sh1[threadIdx.x] += sh1[threadIdx.x + st];
            shq[threadIdx.x] += shq[threadIdx.x + st];
        }
        __syncthreads();
    }
    __shared__ int s_last;
    if (threadIdx.x == 0) {
        g_p1[blockIdx.x] = sh1[0];
        g_p2[blockIdx.x] = shq[0];
        __threadfence();
        unsigned old = atomicAdd(&g_c1, 1u);
        s_last = ((old % NB) == NB - 1);       // replay-safe
    }
    __syncthreads();
    PDL_TRIGGER();   // k_logits can start its independent copy now

    if (s_last) {                              // last block finalizes mu/inv_std
        double t1 = 0.0, t2 = 0.0;
        for (int i = threadIdx.x; i < NB; i += TPB) { t1 += g_p1[i]; t2 += g_p2[i]; }
        sh1[threadIdx.x] = t1; shq[threadIdx.x] = t2;
        __syncthreads();
        for (int st = TPB / 2; st; st >>= 1) {
            if (threadIdx.x < st) {
                sh1[threadIdx.x] += sh1[threadIdx.x + st];
                shq[threadIdx.x] += shq[threadIdx.x + st];
            }
            __syncthreads();
        }
        if (threadIdx.x == 0) {
            double mu  = sh1[0] / (double)E;
            double var = shq[0] / (double)E - mu * mu;
            g_mu  = (float)mu;
            g_inv = (float)rsqrt(var + 1e-5);
        }
    }
}

// ---------------------------------------------------------------------------
// K2: graph row0 copy (vectorized int4->float4, pre-wait: overlaps k_edge
// tail) + logits + sigmoid partial sums; last block publishes inv_mean.
// ---------------------------------------------------------------------------
__global__ __launch_bounds__(TPB) void k_logits(
    const int* __restrict__ gr,
    const float* __restrict__ bw, const float* __restrict__ bb,
    float* __restrict__ out, int E)
{
    const int tid = blockIdx.x * TPB + threadIdx.x;
    const int E4  = E >> 2;

    // graph row 0 -> float out, vectorized (independent of k_edge)
    {
        const int4* __restrict__ gi = (const int4*)gr;
        float4* __restrict__ go = (float4*)out;
        for (int i = tid; i < E4; i += NTHREADS) {
            int4 v = __ldcs(gi + i);
            float4 f = make_float4((float)v.x, (float)v.y, (float)v.z, (float)v.w);
            __stcs(go + i, f);
        }
        for (int i = E4 * 4 + tid; i < E; i += NTHREADS)
            __stcs(out + i, (float)__ldcs(gr + i));
    }

    PDL_WAIT();    // g_mu / g_inv / g_lik now visible

    const float mu = g_mu;
    const float wi = __ldg(bw) * g_inv;
    const float b  = __ldg(bb);

    const float4* __restrict__ lik4 = (const float4*)g_lik;
    float4* __restrict__ lg4 = (float4*)(out + 3LL * E);

    double s = 0.0;

    for (int i = tid; i < E4; i += NTHREADS) {
        float4 l = lik4[i];
        float4 g;
        g.x = fmaf(wi, l.x - mu, b); g.y = fmaf(wi, l.y - mu, b);
        g.z = fmaf(wi, l.z - mu, b); g.w = fmaf(wi, l.w - mu, b);
        __stcs(lg4 + i, g);
        s += (double)((1.0f / (1.0f + __expf(-g.x)) + 1.0f / (1.0f + __expf(-g.y))) +
                      (1.0f / (1.0f + __expf(-g.z)) + 1.0f / (1.0f + __expf(-g.w))));
    }
    for (int e = E4 * 4 + tid; e < E; e += NTHREADS) {
        float lg = fmaf(wi, g_lik[e] - mu, b);
        out[3LL * E + e] = lg;
        s += (double)(1.0f / (1.0f + __expf(-lg)));
    }

    __shared__ double sh[TPB];
    sh[threadIdx.x] = s;
    __syncthreads();
    for (int st = TPB / 2; st; st >>= 1) {
        if (threadIdx.x < st) sh[threadIdx.x] += sh[threadIdx.x + st];
        __syncthreads();
    }
    __shared__ int s_last;
    if (threadIdx.x == 0) {
        g_p3[blockIdx.x] = sh[0];
        __threadfence();
        unsigned old = atomicAdd(&g_c2, 1u);
        s_last = ((old % NB) == NB - 1);
    }
    __syncthreads();
    PDL_TRIGGER();   // k_ew can start its independent copy now

    if (s_last) {
        double t = 0.0;
        for (int i = threadIdx.x; i < NB; i += TPB) t += g_p3[i];
        sh[threadIdx.x] = t;
        __syncthreads();
        for (int st = TPB / 2; st; st >>= 1) {
            if (threadIdx.x < st) sh[threadIdx.x] += sh[threadIdx.x + st];
            __syncthreads();
        }
        if (threadIdx.x == 0) g_im = (float)((double)E / sh[0]);
    }
}

// ---------------------------------------------------------------------------
// K3: graph row1 copy (vectorized, pre-wait) + edge weights (sigmoid
// recomputed from L2-hot logits, scaled by inv_mean).
// ---------------------------------------------------------------------------
__global__ __launch_bounds__(TPB) void k_ew(
    const int* __restrict__ gr, float* __restrict__ out, int E)
{
    const int tid = blockIdx.x * TPB + threadIdx.x;
    const int E4  = E >> 2;

    // graph row 1 -> float out, vectorized (independent of k_logits results)
    {
        const int4* __restrict__ gi = (const int4*)(gr + (size_t)E);
        float4* __restrict__ go = (float4*)(out + (size_t)E);
        for (int i = tid; i < E4; i += NTHREADS) {
            int4 v = __ldcs(gi + i);
            float4 f = make_float4((float)v.x, (float)v.y, (float)v.z, (float)v.w);
            __stcs(go + i, f);
        }
        for (int i = E4 * 4 + tid; i < E; i += NTHREADS)
            __stcs(out + (size_t)E + i, (float)__ldcs(gr + (size_t)E + i));
    }

    PDL_WAIT();    // g_im and logits now visible

    const float im = g_im;
    const float4* __restrict__ lg4 = (const float4*)(out + 3LL * E);
    float4* __restrict__ ew4 = (float4*)(out + 2LL * E);

    for (int i = tid; i < E4; i += NTHREADS) {
        float4 g = __ldcs(lg4 + i);
        float4 v;
        v.x = im / (1.0f + __expf(-g.x)); v.y = im / (1.0f + __expf(-g.y));
        v.z = im / (1.0f + __expf(-g.z)); v.w = im / (1.0f + __expf(-g.w));
        __stcs(ew4 + i, v);
    }
    for (int e = E4 * 4 + tid; e < E; e += NTHREADS)
        out[2LL * E + e] = im / (1.0f + __expf(-out[3LL * E + e]));
}

// ---------------------------------------------------------------------------
template <typename... Args>
static inline void launch_pdl(void (*kern)(Args...), Args... args)
{
    cudaLaunchConfig_t cfg = {};
    cfg.gridDim  = dim3(NB, 1, 1);
    cfg.blockDim = dim3(TPB, 1, 1);
    cudaLaunchAttribute a[1];
    a[0].id = cudaLaunchAttributeProgrammaticStreamSerialization;
    a[0].val.programmaticStreamSerializationAllowed = 1;
    cfg.attrs = a;
    cfg.numAttrs = 1;
    cudaLaunchKernelEx(&cfg, kern, args...);
}

extern "C" void kernel_launch(void* const* d_in, const int* in_sizes, int n_in,
                              void* d_out, int out_size)
{
    const float* src = (const float*)d_in[0];
    const float* dst = (const float*)d_in[1];
    const int*   gr  = (const int*)d_in[2];
    const float* bw  = (const float*)d_in[3];
    const float* bb  = (const float*)d_in[4];
    float* out = (float*)d_out;

    const int E  = in_sizes[2] / 2;
    const int Nn = in_sizes[0] / DD;
    const int total = min(in_sizes[0], 100000 * DD);

    k_conv<<<NB, TPB>>>(src, dst, total);
    launch_pdl(k_edge, gr, E, Nn);
    launch_pdl(k_logits, gr, bw, bb, out, E);
    launch_pdl(k_ew, gr, out, E);
}